// round 1
// baseline (speedup 1.0000x reference)
#include <cuda_runtime.h>
#include <cuda_bf16.h>
#include <cstdint>

// Problem constants
#define N_NODES   2048
#define FDIM      256
#define HID       64
#define TEMPLATE_N 10
#define TRIG_ELEMS (N_NODES * FDIM)          // 524288
#define N_PAIRS   ((N_NODES * (N_NODES - 1)) / 2)  // 2096128

// Scratch (no allocation allowed -> device globals)
__device__ float g_h3[FDIM];
__device__ float g_pa[N_NODES * HID];   // trig @ w1a + eb1
__device__ float g_pb[N_NODES * HID];   // trig @ w1b

// ---------------------------------------------------------------------------
// Kernel 1: proto = mean(clean[sel]) ; h3 = sigmoid(relu(relu(proto@W1+b1)@W2+b2)@W3+b3)
// Single block, 256 threads. Tiny.
// ---------------------------------------------------------------------------
__global__ void __launch_bounds__(256, 1)
k1_mlp(const float* __restrict__ cf, const int* __restrict__ sel,
       const float* __restrict__ w1, const float* __restrict__ b1,
       const float* __restrict__ w2, const float* __restrict__ b2,
       const float* __restrict__ w3, const float* __restrict__ b3)
{
    __shared__ float proto[FDIM];
    __shared__ float h1[HID];
    __shared__ float h2[HID];
    __shared__ float part[256];

    const int tid = threadIdx.x;

    // proto[k] = mean over TEMPLATE_N selected rows
    {
        float s = 0.f;
        #pragma unroll
        for (int t = 0; t < TEMPLATE_N; ++t) {
            int row = sel[t];
            s += cf[(size_t)row * FDIM + tid];
        }
        proto[tid] = s * (1.0f / TEMPLATE_N);
    }
    __syncthreads();

    // h1 = relu(proto @ W1 + b1)  : 256x64. Split the 256-dot 4-ways.
    {
        const int c = tid & 63;
        const int q = tid >> 6;       // 0..3
        float acc = 0.f;
        const int k0 = q * 64;
        #pragma unroll 8
        for (int k = 0; k < 64; ++k)
            acc = fmaf(proto[k0 + k], w1[(k0 + k) * HID + c], acc);
        part[tid] = acc;
    }
    __syncthreads();
    if (tid < HID) {
        float v = part[tid] + part[64 + tid] + part[128 + tid] + part[192 + tid] + b1[tid];
        h1[tid] = fmaxf(v, 0.f);
    }
    __syncthreads();

    // h2 = relu(h1 @ W2 + b2) : 64x64
    if (tid < HID) {
        float acc = b2[tid];
        #pragma unroll 8
        for (int k = 0; k < HID; ++k)
            acc = fmaf(h1[k], w2[k * HID + tid], acc);
        h2[tid] = fmaxf(acc, 0.f);
    }
    __syncthreads();

    // h3 = sigmoid(h2 @ W3 + b3) : 64x256
    {
        float acc = b3[tid];
        #pragma unroll 8
        for (int k = 0; k < HID; ++k)
            acc = fmaf(h2[k], w3[k * FDIM + tid], acc);
        g_h3[tid] = __fdividef(1.0f, 1.0f + __expf(-acc));
    }
}

// ---------------------------------------------------------------------------
// Kernel 2: build trig (write to out) and compute pa = trig@w1a + eb1,
//           pb = trig@w1b. 128 blocks x 256 threads, 16 rows per block.
//   thread: c = tid % 128  (c<64 -> pa column c, else pb column c-64)
//           rh = tid / 128 (0/1) -> 8 rows each
// ---------------------------------------------------------------------------
#define K2_ROWS 16
__global__ void __launch_bounds__(256, 1)
k2_trig_pab(const float* __restrict__ noise,
            const float* __restrict__ ew1,
            const float* __restrict__ eb1,
            float* __restrict__ out_trig)
{
    __shared__ float trS[K2_ROWS * FDIM];   // 16 KB

    const int tid = threadIdx.x;
    const int r0  = blockIdx.x * K2_ROWS;

    // Phase 1: materialize trig rows r0..r0+15, write to out, keep in shared
    for (int idx = tid; idx < K2_ROWS * FDIM; idx += 256) {
        const int r = r0 + (idx >> 8);       // /256
        const int k = idx & 255;
        float v = g_h3[k];
        if (r >= TEMPLATE_N)
            v = fmaf(0.1f, noise[(size_t)(r - TEMPLATE_N) * FDIM + k], v);
        trS[idx] = v;
        out_trig[(size_t)r * FDIM + k] = v;
    }
    __syncthreads();

    // Phase 2: dot products along k=256 with column-coalesced weight loads.
    const int c  = tid & 127;
    const int rh = tid >> 7;                 // 0 or 1
    const bool is_pa = (c < HID);
    const float* wcol = ew1 + (is_pa ? c : (FDIM * HID + (c - HID)));

    float acc[8];
    #pragma unroll
    for (int u = 0; u < 8; ++u) acc[u] = 0.f;

    const float* trBase = trS + (rh * 8) * FDIM;
    #pragma unroll 4
    for (int k = 0; k < FDIM; ++k) {
        const float w = wcol[k * HID];       // coalesced across c
        #pragma unroll
        for (int u = 0; u < 8; ++u)
            acc[u] = fmaf(trBase[u * FDIM + k], w, acc[u]);
    }

    const float bias = is_pa ? eb1[c] : 0.f;
    #pragma unroll
    for (int u = 0; u < 8; ++u) {
        const int row = r0 + rh * 8 + u;
        if (is_pa) g_pa[row * HID + c]         = acc[u] + bias;
        else       g_pb[row * HID + (c - HID)] = acc[u];
    }
}

// ---------------------------------------------------------------------------
// Kernel 3: the pair kernel.
//   edge(i,j) = sigmoid( sum_k relu(pa[i][k] + pb[j][k]) * w2[k] + eb2 ),  j > i
//   output index = i*(2N-i-1)/2 + (j-i-1)   (row-major triu order)
// Tile: 64 i's (shared) x 256 j's (one per thread, pb+w2 in registers).
// Stores are contiguous in j -> fully coalesced.
// ---------------------------------------------------------------------------
#define TI 64
#define TJ 256
__global__ void __launch_bounds__(256, 1)
k3_pairs(const float* __restrict__ ew2,
         const float* __restrict__ eb2,
         float* __restrict__ out_edge)
{
    const int jt = blockIdx.x;       // 0..7
    const int it = blockIdx.y;       // 0..31
    const int i0 = it * TI;
    const int j0 = jt * TJ;

    // Tile entirely below/at diagonal -> nothing to do
    if (j0 + TJ - 1 <= i0) return;

    __shared__ float paS[TI * HID];  // 16 KB
    const int tid = threadIdx.x;

    for (int idx = tid; idx < TI * HID; idx += 256)
        paS[idx] = g_pa[i0 * HID + idx];
    __syncthreads();

    const int j = j0 + tid;

    // pb row and w2 into registers (float4)
    float4 pb4[16], w24[16];
    {
        const float4* pbp = (const float4*)(g_pb + j * HID);
        const float4* w2p = (const float4*)ew2;
        #pragma unroll
        for (int q = 0; q < 16; ++q) { pb4[q] = pbp[q]; w24[q] = __ldg(&w2p[q]); }
    }
    const float ebb = eb2[0];

    const int iiEnd = min(TI, j0 + TJ - 1 - i0);   // need i < j0+TJ-1 possible... i < max_j

    const float4* paS4 = (const float4*)paS;

    for (int ii = 0; ii < iiEnd; ++ii) {
        const int i = i0 + ii;
        float a0 = 0.f, a1 = 0.f, a2 = 0.f, a3 = 0.f;
        const float4* pap = paS4 + ii * 16;
        #pragma unroll
        for (int q = 0; q < 16; ++q) {
            const float4 p = pap[q];          // LDS broadcast (uniform per warp)
            const float4 b = pb4[q];
            const float4 w = w24[q];
            float t;
            t = fmaxf(p.x + b.x, 0.f); a0 = fmaf(t, w.x, a0);
            t = fmaxf(p.y + b.y, 0.f); a1 = fmaf(t, w.y, a1);
            t = fmaxf(p.z + b.z, 0.f); a2 = fmaf(t, w.z, a2);
            t = fmaxf(p.w + b.w, 0.f); a3 = fmaf(t, w.w, a3);
        }
        if (j > i) {
            const float s = (a0 + a1) + (a2 + a3) + ebb;
            const float pr = __fdividef(1.0f, 1.0f + __expf(-s));
            const int base = i * (2 * N_NODES - i - 1) / 2;   // i*(4095-i)/2
            out_edge[base + (j - i - 1)] = pr;
        }
    }
}

// ---------------------------------------------------------------------------
extern "C" void kernel_launch(void* const* d_in, const int* in_sizes, int n_in,
                              void* d_out, int out_size)
{
    const float* cf    = (const float*)d_in[0];
    const int*   sel   = (const int*)  d_in[1];
    const float* noise = (const float*)d_in[2];
    const float* g1w   = (const float*)d_in[3];
    const float* g1b   = (const float*)d_in[4];
    const float* g2w   = (const float*)d_in[5];
    const float* g2b   = (const float*)d_in[6];
    const float* g3w   = (const float*)d_in[7];
    const float* g3b   = (const float*)d_in[8];
    const float* ew1   = (const float*)d_in[9];
    const float* eb1   = (const float*)d_in[10];
    const float* ew2   = (const float*)d_in[11];
    const float* eb2   = (const float*)d_in[12];

    float* out      = (float*)d_out;
    float* out_trig = out;
    float* out_edge = out + TRIG_ELEMS;

    k1_mlp<<<1, 256>>>(cf, sel, g1w, g1b, g2w, g2b, g3w, g3b);
    k2_trig_pab<<<N_NODES / K2_ROWS, 256>>>(noise, ew1, eb1, out_trig);
    k3_pairs<<<dim3(N_NODES / TJ, N_NODES / TI), 256>>>(ew2, eb2, out_edge);
}

// round 2
// speedup vs baseline: 1.0230x; 1.0230x over previous
#include <cuda_runtime.h>
#include <cuda_bf16.h>
#include <cstdint>

#define N_NODES    2048
#define FDIM       256
#define HID        64
#define TEMPLATE_N 10
#define TRIG_ELEMS (N_NODES * FDIM)
#define EW1B_OFF   (FDIM * HID)          // offset of w1b inside ew1

// device scratch (no allocs allowed)
__device__ float g_h3[FDIM];
__device__ float g_base[HID];            // h3@w1a + h3@w1b + eb1
__device__ float g_npa[N_NODES * HID];   // 0.1*noise@w1a (rows 0..9 zero)
__device__ float g_npb[N_NODES * HID];   // 0.1*noise@w1b (rows 0..9 zero)

// ---- f32x2 packed helpers (sm_100+) --------------------------------------
__device__ __forceinline__ unsigned long long f2_add(unsigned long long a, unsigned long long b) {
    unsigned long long r; asm("add.rn.f32x2 %0, %1, %2;" : "=l"(r) : "l"(a), "l"(b)); return r;
}
__device__ __forceinline__ unsigned long long f2_fma(unsigned long long a, unsigned long long b, unsigned long long c) {
    unsigned long long r; asm("fma.rn.f32x2 %0, %1, %2, %3;" : "=l"(r) : "l"(a), "l"(b), "l"(c)); return r;
}
__device__ __forceinline__ void f2_unpack(float& lo, float& hi, unsigned long long v) {
    asm("mov.b64 {%0, %1}, %2;" : "=f"(lo), "=f"(hi) : "l"(v));
}
__device__ __forceinline__ unsigned long long f2_pack(float lo, float hi) {
    unsigned long long r; asm("mov.b64 %0, {%1, %2};" : "=l"(r) : "f"(lo), "f"(hi)); return r;
}

// ---------------------------------------------------------------------------
// k1: proto mean -> 3-layer MLP -> h3 ; base = h3@(w1a+w1b)+eb1
// One block, 1024 threads. Every phase does ONE parallel load round + smem
// tree reduce, so latency is ~5 memory rounds, not 5x64 chained loads.
// ---------------------------------------------------------------------------
__global__ void __launch_bounds__(1024, 1)
k1_mlp(const float* __restrict__ cf, const int* __restrict__ sel,
       const float* __restrict__ w1, const float* __restrict__ b1,
       const float* __restrict__ w2, const float* __restrict__ b2,
       const float* __restrict__ w3, const float* __restrict__ b3,
       const float* __restrict__ ew1, const float* __restrict__ eb1)
{
    __shared__ float proto[FDIM];
    __shared__ float h1[HID];
    __shared__ float h2[HID];
    __shared__ float h3S[FDIM];
    __shared__ float part[1024];

    const int t = threadIdx.x;

    // Phase A: proto = mean of 10 gathered rows. 4-way row split per column.
    {
        const int k = t & 255;
        const int g = t >> 8;                    // 0..3
        float s = 0.f;
        if (g < 3) {
            #pragma unroll
            for (int r = 0; r < 3; ++r) {
                int row = sel[3 * g + r];
                s += cf[(size_t)row * FDIM + k];
            }
        } else {
            int row = sel[9];
            s = cf[(size_t)row * FDIM + k];
        }
        part[t] = s;
    }
    __syncthreads();
    if (t < 256)
        proto[t] = (part[t] + part[256 + t] + part[512 + t] + part[768 + t]) * (1.0f / TEMPLATE_N);
    __syncthreads();

    // Phase B: h1 = relu(proto @ W1 + b1). 64 cols, 16-way k split (16 k each).
    {
        const int c = t & 63, q = t >> 6;        // q 0..15
        const int k0 = q * 16;
        float acc = 0.f;
        #pragma unroll
        for (int k = 0; k < 16; ++k)
            acc = fmaf(proto[k0 + k], w1[(k0 + k) * HID + c], acc);
        part[t] = acc;
    }
    __syncthreads();
    if (t < HID) {
        float s = b1[t];
        #pragma unroll
        for (int q = 0; q < 16; ++q) s += part[q * 64 + t];
        h1[t] = fmaxf(s, 0.f);
    }
    __syncthreads();

    // Phase C: h2 = relu(h1 @ W2 + b2). 64 cols, 16-way split over k=64.
    {
        const int c = t & 63, q = t >> 6;
        const int k0 = q * 4;
        float acc = 0.f;
        #pragma unroll
        for (int k = 0; k < 4; ++k)
            acc = fmaf(h1[k0 + k], w2[(k0 + k) * HID + c], acc);
        part[t] = acc;
    }
    __syncthreads();
    if (t < HID) {
        float s = b2[t];
        #pragma unroll
        for (int q = 0; q < 16; ++q) s += part[q * 64 + t];
        h2[t] = fmaxf(s, 0.f);
    }
    __syncthreads();

    // Phase D: h3 = sigmoid(h2 @ W3 + b3). 256 cols, 4-way split over k=64.
    {
        const int c = t & 255, q = t >> 8;
        const int k0 = q * 16;
        float acc = 0.f;
        #pragma unroll
        for (int k = 0; k < 16; ++k)
            acc = fmaf(h2[k0 + k], w3[(k0 + k) * FDIM + c], acc);
        part[t] = acc;
    }
    __syncthreads();
    if (t < 256) {
        float s = b3[t] + part[t] + part[256 + t] + part[512 + t] + part[768 + t];
        float v = __fdividef(1.0f, 1.0f + __expf(-s));
        g_h3[t] = v;
        h3S[t]  = v;
    }
    __syncthreads();

    // Phase E: base[c] = sum_k h3[k]*(w1a[k][c]+w1b[k][c]) + eb1[c]
    {
        const int c = t & 63, q = t >> 6;        // 16-way over k=256
        const int k0 = q * 16;
        float acc = 0.f;
        #pragma unroll
        for (int k = 0; k < 16; ++k) {
            float w = ew1[(k0 + k) * HID + c] + ew1[EW1B_OFF + (k0 + k) * HID + c];
            acc = fmaf(h3S[k0 + k], w, acc);
        }
        part[t] = acc;
    }
    __syncthreads();
    if (t < HID) {
        float s = eb1[t];
        #pragma unroll
        for (int q = 0; q < 16; ++q) s += part[q * 64 + t];
        g_base[t] = s;
    }
}

// ---------------------------------------------------------------------------
// kAB: per block of 16 output rows:
//   nS[k][r] = (r>=10) ? 0.1*noise[r-10][k] : 0        (k-major, padded)
//   out_trig[r][k] = h3[k] + nS[k][r]
//   g_npa[r] = nS^T @ w1a ; g_npb[r] = nS^T @ w1b      (FFMA2 on row pairs)
// 128 blocks x 256 threads.
// ---------------------------------------------------------------------------
#define KAB_ROWS 16
#define NS_STRIDE 20   // 16 rows + pad, keeps 16B alignment for ulonglong2
__global__ void __launch_bounds__(256, 1)
kAB_noise(const float* __restrict__ noise,
          const float* __restrict__ ew1,
          float* __restrict__ out_trig)
{
    __shared__ float nS[FDIM * NS_STRIDE];   // 20 KB

    const int tid = threadIdx.x;
    const int r0  = blockIdx.x * KAB_ROWS;

    // Phase 1: fill nS (k-major) and write trig rows.
    const float h3v = g_h3[tid];             // k == tid (256 threads)
    #pragma unroll
    for (int u = 0; u < KAB_ROWS; ++u) {
        const int r = r0 + u;
        float v = 0.f;
        if (r >= TEMPLATE_N)
            v = 0.1f * noise[(size_t)(r - TEMPLATE_N) * FDIM + tid];
        nS[tid * NS_STRIDE + u] = v;
        out_trig[(size_t)r * FDIM + tid] = h3v + v;
    }
    __syncthreads();

    // Phase 2: GEMM. c = tid&127 (col: <64 -> pa, else pb), rh = tid>>7 (row half).
    const int c  = tid & 127;
    const int rh = tid >> 7;
    const bool is_pa = (c < HID);
    const float* wcol = ew1 + (is_pa ? c : (EW1B_OFF + (c - HID)));

    unsigned long long acc[4];
    #pragma unroll
    for (int p = 0; p < 4; ++p) acc[p] = f2_pack(0.f, 0.f);

    #pragma unroll 4
    for (int k = 0; k < FDIM; ++k) {
        const float w = wcol[k * HID];                     // coalesced across c
        const unsigned long long wp = f2_pack(w, w);
        const float* base = nS + k * NS_STRIDE + rh * 8;
        const ulonglong2 A = *reinterpret_cast<const ulonglong2*>(base);      // rows 0-3
        const ulonglong2 B = *reinterpret_cast<const ulonglong2*>(base + 4);  // rows 4-7
        acc[0] = f2_fma(A.x, wp, acc[0]);
        acc[1] = f2_fma(A.y, wp, acc[1]);
        acc[2] = f2_fma(B.x, wp, acc[2]);
        acc[3] = f2_fma(B.y, wp, acc[3]);
    }

    float* dst = (is_pa ? g_npa : g_npb);
    const int cc = is_pa ? c : (c - HID);
    #pragma unroll
    for (int p = 0; p < 4; ++p) {
        float lo, hi;
        f2_unpack(lo, hi, acc[p]);
        const int row = r0 + rh * 8 + 2 * p;
        dst[row * HID + cc]       = lo;
        dst[(row + 1) * HID + cc] = hi;
    }
}

// ---------------------------------------------------------------------------
// k3: edge(i,j) = sigmoid( sum_k relu(base[k]+npa[i][k]+npb[j][k]) * w2[k] + eb2 )
// base folded into the shared pa tile. Packed f32x2 add/fma; scalar relu (alu pipe).
// TJ=128 threads (thread owns j), TI=64 i's per block. Stores coalesced in j.
// ---------------------------------------------------------------------------
#define TI 64
#define TJ 128
__global__ void __launch_bounds__(TJ)
k3_pairs(const float* __restrict__ ew2,
         const float* __restrict__ eb2,
         float* __restrict__ out_edge)
{
    const int j0 = blockIdx.x * TJ;
    const int i0 = blockIdx.y * TI;
    if (j0 + TJ - 1 <= i0) return;           // fully at/below diagonal

    __shared__ float paS[TI * HID];          // 16 KB
    const int tid = threadIdx.x;

    for (int idx = tid; idx < TI * HID; idx += TJ)
        paS[idx] = g_npa[i0 * HID + idx] + __ldg(&g_base[idx & (HID - 1)]);
    __syncthreads();

    const int j = j0 + tid;

    unsigned long long pb2[32], w22[32];
    {
        const ulonglong2* pbp = reinterpret_cast<const ulonglong2*>(g_npb + j * HID);
        const ulonglong2* w2p = reinterpret_cast<const ulonglong2*>(ew2);
        #pragma unroll
        for (int q = 0; q < 16; ++q) {
            ulonglong2 a = pbp[q];       pb2[2 * q] = a.x; pb2[2 * q + 1] = a.y;
            ulonglong2 b = __ldg(&w2p[q]); w22[2 * q] = b.x; w22[2 * q + 1] = b.y;
        }
    }
    const float ebb = eb2[0];

    const int iiEnd = min(TI, j0 + TJ - 1 - i0);
    const ulonglong2* paS2 = reinterpret_cast<const ulonglong2*>(paS);

    for (int ii = 0; ii < iiEnd; ++ii) {
        const int i = i0 + ii;
        unsigned long long a0 = f2_pack(0.f, 0.f), a1 = a0, a2 = a0, a3 = a0;
        const ulonglong2* pap = paS2 + ii * 16;
        #pragma unroll
        for (int q = 0; q < 16; ++q) {
            const ulonglong2 P = pap[q];                  // LDS.128 broadcast
            unsigned long long t0 = f2_add(P.x, pb2[2 * q]);
            unsigned long long t1 = f2_add(P.y, pb2[2 * q + 1]);
            float l0, h0, l1, h1;
            f2_unpack(l0, h0, t0);
            f2_unpack(l1, h1, t1);
            l0 = fmaxf(l0, 0.f); h0 = fmaxf(h0, 0.f);
            l1 = fmaxf(l1, 0.f); h1 = fmaxf(h1, 0.f);
            t0 = f2_pack(l0, h0);
            t1 = f2_pack(l1, h1);
            unsigned long long* A = (q & 1) ? &a2 : &a0;
            unsigned long long* B = (q & 1) ? &a3 : &a1;
            *A = f2_fma(t0, w22[2 * q], *A);
            *B = f2_fma(t1, w22[2 * q + 1], *B);
        }
        if (j > i) {
            float s0, s1, s2, s3, s4, s5, s6, s7;
            f2_unpack(s0, s1, a0); f2_unpack(s2, s3, a1);
            f2_unpack(s4, s5, a2); f2_unpack(s6, s7, a3);
            const float s = ((s0 + s1) + (s2 + s3)) + ((s4 + s5) + (s6 + s7)) + ebb;
            const float pr = __fdividef(1.0f, 1.0f + __expf(-s));
            const int base = i * (2 * N_NODES - i - 1) / 2;
            out_edge[base + (j - i - 1)] = pr;
        }
    }
}

// ---------------------------------------------------------------------------
extern "C" void kernel_launch(void* const* d_in, const int* in_sizes, int n_in,
                              void* d_out, int out_size)
{
    const float* cf    = (const float*)d_in[0];
    const int*   sel   = (const int*)  d_in[1];
    const float* noise = (const float*)d_in[2];
    const float* g1w   = (const float*)d_in[3];
    const float* g1b   = (const float*)d_in[4];
    const float* g2w   = (const float*)d_in[5];
    const float* g2b   = (const float*)d_in[6];
    const float* g3w   = (const float*)d_in[7];
    const float* g3b   = (const float*)d_in[8];
    const float* ew1   = (const float*)d_in[9];
    const float* eb1   = (const float*)d_in[10];
    const float* ew2   = (const float*)d_in[11];
    const float* eb2   = (const float*)d_in[12];

    float* out      = (float*)d_out;
    float* out_trig = out;
    float* out_edge = out + TRIG_ELEMS;

    k1_mlp<<<1, 1024>>>(cf, sel, g1w, g1b, g2w, g2b, g3w, g3b, ew1, eb1);
    kAB_noise<<<N_NODES / KAB_ROWS, 256>>>(noise, ew1, out_trig);
    k3_pairs<<<dim3(N_NODES / TJ, N_NODES / TI), TJ>>>(ew2, eb2, out_edge);
}

// round 3
// speedup vs baseline: 1.4234x; 1.3914x over previous
#include <cuda_runtime.h>
#include <cuda_fp16.h>
#include <cstdint>

#define N_NODES    2048
#define FDIM       256
#define HID        64
#define TEMPLATE_N 10
#define TRIG_ELEMS (N_NODES * FDIM)
#define EW1B_OFF   (FDIM * HID)

// device scratch
__device__ float g_h3[FDIM];
__device__ float g_base[HID];            // h3@(w1a+w1b) + eb1
__device__ float g_npa[N_NODES * HID];   // 0.1*noise@w1a (rows 0..9 zero)
__device__ float g_npb[N_NODES * HID];   // 0.1*noise@w1b (rows 0..9 zero)

// ---- f32x2 helpers (used only in the prep GEMM, no relu there) ------------
__device__ __forceinline__ unsigned long long f2_fma(unsigned long long a, unsigned long long b, unsigned long long c) {
    unsigned long long r; asm("fma.rn.f32x2 %0, %1, %2, %3;" : "=l"(r) : "l"(a), "l"(b), "l"(c)); return r;
}
__device__ __forceinline__ void f2_unpack(float& lo, float& hi, unsigned long long v) {
    asm("mov.b64 {%0, %1}, %2;" : "=f"(lo), "=f"(hi) : "l"(v));
}
__device__ __forceinline__ unsigned long long f2_pack(float lo, float hi) {
    unsigned long long r; asm("mov.b64 %0, {%1, %2};" : "=l"(r) : "f"(lo), "f"(hi)); return r;
}

// ---------------------------------------------------------------------------
// Kernel P: 129 blocks x 256 threads.
//   block 0   : MLP -> g_h3, g_base    (hidden under the GEMM blocks)
//   blocks 1+ : noise GEMM -> g_npa/g_npb   (independent of the MLP)
// ---------------------------------------------------------------------------
#define KP_ROWS  16
#define NS_STRIDE 20   // 16 + pad, keeps 16B alignment

__global__ void __launch_bounds__(256, 1)
kP_prep(const float* __restrict__ cf, const int* __restrict__ sel,
        const float* __restrict__ w1, const float* __restrict__ b1,
        const float* __restrict__ w2, const float* __restrict__ b2,
        const float* __restrict__ w3, const float* __restrict__ b3,
        const float* __restrict__ ew1, const float* __restrict__ eb1,
        const float* __restrict__ noise)
{
    __shared__ float sBuf[FDIM * NS_STRIDE];   // 20 KB, aliased by both roles
    const int tid = threadIdx.x;

    if (blockIdx.x == 0) {
        // ---------------- MLP ----------------
        float* proto = sBuf;            // 256
        float* h1    = sBuf + 256;      // 64
        float* h2    = sBuf + 320;      // 64
        float* h3S   = sBuf + 384;      // 256
        float* part  = sBuf + 640;      // 256

        // proto[k] = mean of 10 gathered rows (k = tid)
        {
            int rows[TEMPLATE_N];
            #pragma unroll
            for (int r = 0; r < TEMPLATE_N; ++r) rows[r] = sel[r];
            float s = 0.f;
            #pragma unroll
            for (int r = 0; r < TEMPLATE_N; ++r)
                s += cf[(size_t)rows[r] * FDIM + tid];
            proto[tid] = s * (1.0f / TEMPLATE_N);
        }
        __syncthreads();

        // h1 = relu(proto @ W1 + b1) : 4-way k split
        {
            const int c = tid & 63, q = tid >> 6, k0 = q * 64;
            float acc = 0.f;
            #pragma unroll 8
            for (int k = 0; k < 64; ++k)
                acc = fmaf(proto[k0 + k], w1[(k0 + k) * HID + c], acc);
            part[tid] = acc;
        }
        __syncthreads();
        if (tid < HID)
            h1[tid] = fmaxf(part[tid] + part[64 + tid] + part[128 + tid] + part[192 + tid] + b1[tid], 0.f);
        __syncthreads();

        // h2 = relu(h1 @ W2 + b2) : 4-way split over k=64
        {
            const int c = tid & 63, q = tid >> 6, k0 = q * 16;
            float acc = 0.f;
            #pragma unroll
            for (int k = 0; k < 16; ++k)
                acc = fmaf(h1[k0 + k], w2[(k0 + k) * HID + c], acc);
            part[tid] = acc;
        }
        __syncthreads();
        if (tid < HID)
            h2[tid] = fmaxf(part[tid] + part[64 + tid] + part[128 + tid] + part[192 + tid] + b2[tid], 0.f);
        __syncthreads();

        // h3 = sigmoid(h2 @ W3 + b3) : c = tid, chain over k=64
        {
            float acc = b3[tid];
            #pragma unroll 8
            for (int k = 0; k < HID; ++k)
                acc = fmaf(h2[k], w3[k * FDIM + tid], acc);
            float v = __fdividef(1.0f, 1.0f + __expf(-acc));
            g_h3[tid] = v;
            h3S[tid]  = v;
        }
        __syncthreads();

        // base[c] = sum_k h3[k]*(w1a[k][c]+w1b[k][c]) + eb1[c] : 4-way k split
        {
            const int c = tid & 63, q = tid >> 6, k0 = q * 64;
            float acc = 0.f;
            #pragma unroll 4
            for (int k = 0; k < 64; ++k) {
                float w = ew1[(k0 + k) * HID + c] + ew1[EW1B_OFF + (k0 + k) * HID + c];
                acc = fmaf(h3S[k0 + k], w, acc);
            }
            part[tid] = acc;
        }
        __syncthreads();
        if (tid < HID)
            g_base[tid] = part[tid] + part[64 + tid] + part[128 + tid] + part[192 + tid] + eb1[tid];
        return;
    }

    // ---------------- noise GEMM (blocks 1..128) ----------------
    float* nS = sBuf;                       // [FDIM][NS_STRIDE] k-major
    const int r0 = (blockIdx.x - 1) * KP_ROWS;

    #pragma unroll
    for (int u = 0; u < KP_ROWS; ++u) {
        const int r = r0 + u;
        float v = 0.f;
        if (r >= TEMPLATE_N)
            v = 0.1f * noise[(size_t)(r - TEMPLATE_N) * FDIM + tid];
        nS[tid * NS_STRIDE + u] = v;
    }
    __syncthreads();

    const int c  = tid & 127;
    const int rh = tid >> 7;
    const bool is_pa = (c < HID);
    const float* wcol = ew1 + (is_pa ? c : (EW1B_OFF + (c - HID)));

    unsigned long long acc[4];
    #pragma unroll
    for (int p = 0; p < 4; ++p) acc[p] = f2_pack(0.f, 0.f);

    #pragma unroll 4
    for (int k = 0; k < FDIM; ++k) {
        const float w = wcol[k * HID];
        const unsigned long long wp = f2_pack(w, w);
        const float* base = nS + k * NS_STRIDE + rh * 8;
        const ulonglong2 A = *reinterpret_cast<const ulonglong2*>(base);
        const ulonglong2 B = *reinterpret_cast<const ulonglong2*>(base + 4);
        acc[0] = f2_fma(A.x, wp, acc[0]);
        acc[1] = f2_fma(A.y, wp, acc[1]);
        acc[2] = f2_fma(B.x, wp, acc[2]);
        acc[3] = f2_fma(B.y, wp, acc[3]);
    }

    float* dst = (is_pa ? g_npa : g_npb);
    const int cc = is_pa ? c : (c - HID);
    #pragma unroll
    for (int p = 0; p < 4; ++p) {
        float lo, hi;
        f2_unpack(lo, hi, acc[p]);
        const int row = r0 + rh * 8 + 2 * p;
        dst[row * HID + cc]       = lo;
        dst[(row + 1) * HID + cc] = hi;
    }
}

// ---------------------------------------------------------------------------
// Kernel E: 144 blocks (one per useful 256j x 64i tile) x 256 threads.
//   stage 0: write out_trig rows (round-robin over blocks)
//   stage 1: pa tile (base+npa -> fp16) into smem; pb row + w2 -> fp16 regs
//   stage 2: pair loop: h = hfma2_relu(pa, 1, pb); acc = hfma2(h, w2, acc)
// ---------------------------------------------------------------------------
#define TI 64
#define TJ 256
#define N_TILES 144

__global__ void __launch_bounds__(TJ, 1)
kE_edges(const float* __restrict__ noise,
         const float* __restrict__ ew2,
         const float* __restrict__ eb2,
         float* __restrict__ out_trig,
         float* __restrict__ out_edge)
{
    __shared__ __half2 paS[TI * 32];          // 8 KB
    const int tid = threadIdx.x;

    // ---- stage 0: trig rows ----
    {
        const float h3v = g_h3[tid];
        for (int r = blockIdx.x; r < N_NODES; r += N_TILES) {
            float v = h3v;
            if (r >= TEMPLATE_N)
                v = fmaf(0.1f, noise[(size_t)(r - TEMPLATE_N) * FDIM + tid], v);
            out_trig[(size_t)r * FDIM + tid] = v;
        }
    }

    // ---- tile mapping: block -> (jt, it), only tiles with j0+255 > i0 ----
    int rem = blockIdx.x, jt = 0;
    for (jt = 0; jt < 8; ++jt) { int n = 4 * jt + 4; if (rem < n) break; rem -= n; }
    const int it = rem;
    const int j0 = jt * TJ;
    const int i0 = it * TI;

    // ---- stage 1a: pa tile -> fp16 smem (base folded in, fp32 add) ----
    for (int idx = tid; idx < TI * 32; idx += TJ) {
        const int ii = idx >> 5, kp = idx & 31;
        const float lo = g_npa[(i0 + ii) * HID + 2 * kp]     + g_base[2 * kp];
        const float hi = g_npa[(i0 + ii) * HID + 2 * kp + 1] + g_base[2 * kp + 1];
        paS[idx] = __floats2half2_rn(lo, hi);
    }

    // ---- stage 1b: pb row + w2 -> fp16 regs ----
    const int j = j0 + tid;
    __half2 pb2[32], w2h[32];
    {
        const float4* pbp = reinterpret_cast<const float4*>(g_npb + j * HID);
        const float4* w2p = reinterpret_cast<const float4*>(ew2);
        #pragma unroll
        for (int q = 0; q < 16; ++q) {
            float4 v = pbp[q];
            pb2[2 * q]     = __floats2half2_rn(v.x, v.y);
            pb2[2 * q + 1] = __floats2half2_rn(v.z, v.w);
            float4 w = __ldg(&w2p[q]);
            w2h[2 * q]     = __floats2half2_rn(w.x, w.y);
            w2h[2 * q + 1] = __floats2half2_rn(w.z, w.w);
        }
    }
    const float ebb = eb2[0];
    const __half2 one2 = __floats2half2_rn(1.0f, 1.0f);
    __syncthreads();

    // ---- stage 2: pair loop ----
    const int iiEnd = min(TI, j0 + TJ - 1 - i0);
    const uint4* paS4 = reinterpret_cast<const uint4*>(paS);   // 4 half2 per uint4

    for (int ii = 0; ii < iiEnd; ++ii) {
        const int i = i0 + ii;
        __half2 a0 = __float2half2_rn(0.f), a1 = a0, a2 = a0, a3 = a0;

        #pragma unroll
        for (int q = 0; q < 8; ++q) {
            const uint4 P = paS4[ii * 8 + q];                  // LDS.128 broadcast
            const __half2 p0 = *reinterpret_cast<const __half2*>(&P.x);
            const __half2 p1 = *reinterpret_cast<const __half2*>(&P.y);
            const __half2 p2 = *reinterpret_cast<const __half2*>(&P.z);
            const __half2 p3 = *reinterpret_cast<const __half2*>(&P.w);
            const int kp = q * 4;
            __half2 h;
            h = __hfma2_relu(p0, one2, pb2[kp + 0]); a0 = __hfma2(h, w2h[kp + 0], a0);
            h = __hfma2_relu(p1, one2, pb2[kp + 1]); a1 = __hfma2(h, w2h[kp + 1], a1);
            h = __hfma2_relu(p2, one2, pb2[kp + 2]); a2 = __hfma2(h, w2h[kp + 2], a2);
            h = __hfma2_relu(p3, one2, pb2[kp + 3]); a3 = __hfma2(h, w2h[kp + 3], a3);
        }

        if (j > i) {
            const __half2 s01 = __hadd2(a0, a1);
            const __half2 s23 = __hadd2(a2, a3);
            const __half2 st  = __hadd2(s01, s23);
            const float2 f = __half22float2(st);
            const float s = f.x + f.y + ebb;
            const float pr = __fdividef(1.0f, 1.0f + __expf(-s));
            const int base = i * (2 * N_NODES - i - 1) / 2;
            out_edge[base + (j - i - 1)] = pr;
        }
    }
}

// ---------------------------------------------------------------------------
extern "C" void kernel_launch(void* const* d_in, const int* in_sizes, int n_in,
                              void* d_out, int out_size)
{
    const float* cf    = (const float*)d_in[0];
    const int*   sel   = (const int*)  d_in[1];
    const float* noise = (const float*)d_in[2];
    const float* g1w   = (const float*)d_in[3];
    const float* g1b   = (const float*)d_in[4];
    const float* g2w   = (const float*)d_in[5];
    const float* g2b   = (const float*)d_in[6];
    const float* g3w   = (const float*)d_in[7];
    const float* g3b   = (const float*)d_in[8];
    const float* ew1   = (const float*)d_in[9];
    const float* eb1   = (const float*)d_in[10];
    const float* ew2   = (const float*)d_in[11];
    const float* eb2   = (const float*)d_in[12];

    float* out      = (float*)d_out;
    float* out_trig = out;
    float* out_edge = out + TRIG_ELEMS;

    kP_prep<<<129, 256>>>(cf, sel, g1w, g1b, g2w, g2b, g3w, g3b, ew1, eb1, noise);
    kE_edges<<<N_TILES, TJ>>>(noise, ew2, eb2, out_trig, out_edge);
}

// round 4
// speedup vs baseline: 1.7724x; 1.2451x over previous
#include <cuda_runtime.h>
#include <cuda_fp16.h>
#include <cstdint>

#define N_NODES    2048
#define FDIM       256
#define HID        64
#define TEMPLATE_N 10
#define TRIG_ELEMS (N_NODES * FDIM)
#define EW1B_OFF   (FDIM * HID)

// device scratch
__device__ float g_h3[FDIM];
__device__ float g_base[HID];            // h3@(w1a+w1b) + eb1
__device__ float g_npa[N_NODES * HID];   // 0.1*noise@w1a (rows 0..9 zero)
__device__ float g_npb[N_NODES * HID];   // 0.1*noise@w1b (rows 0..9 zero)

// ---- f32x2 helpers (prep GEMM only) --------------------------------------
__device__ __forceinline__ unsigned long long f2_fma(unsigned long long a, unsigned long long b, unsigned long long c) {
    unsigned long long r; asm("fma.rn.f32x2 %0, %1, %2, %3;" : "=l"(r) : "l"(a), "l"(b), "l"(c)); return r;
}
__device__ __forceinline__ void f2_unpack(float& lo, float& hi, unsigned long long v) {
    asm("mov.b64 {%0, %1}, %2;" : "=f"(lo), "=f"(hi) : "l"(v));
}
__device__ __forceinline__ unsigned long long f2_pack(float lo, float hi) {
    unsigned long long r; asm("mov.b64 %0, {%1, %2};" : "=l"(r) : "f"(lo), "f"(hi)); return r;
}

// ---------------------------------------------------------------------------
// Kernel P: 257 blocks x 256 threads, 2 CTAs/SM.
//   block 0   : MLP -> g_h3, g_base (hidden under the GEMM blocks)
//   blocks 1+ : noise GEMM, 8 rows/block -> g_npa/g_npb
// ---------------------------------------------------------------------------
#define KP_ROWS   8
#define NS_STRIDE 12   // 8 rows + pad; k*12 is a multiple of 4 floats -> 16B aligned

__global__ void __launch_bounds__(256, 2)
kP_prep(const float* __restrict__ cf, const int* __restrict__ sel,
        const float* __restrict__ w1, const float* __restrict__ b1,
        const float* __restrict__ w2, const float* __restrict__ b2,
        const float* __restrict__ w3, const float* __restrict__ b3,
        const float* __restrict__ ew1, const float* __restrict__ eb1,
        const float* __restrict__ noise)
{
    __shared__ float sBuf[FDIM * NS_STRIDE];   // 12 KB
    const int tid = threadIdx.x;

    if (blockIdx.x == 0) {
        // ---------------- MLP ----------------
        float* proto = sBuf;            // 256
        float* h1    = sBuf + 256;      // 64
        float* h2    = sBuf + 320;      // 64
        float* h3S   = sBuf + 384;      // 256
        float* part  = sBuf + 640;      // 256

        {
            float s = 0.f;
            #pragma unroll
            for (int r = 0; r < TEMPLATE_N; ++r)
                s += cf[(size_t)sel[r] * FDIM + tid];
            proto[tid] = s * (1.0f / TEMPLATE_N);
        }
        __syncthreads();

        // h1 = relu(proto @ W1 + b1), 4-way k split
        {
            const int c = tid & 63, q = tid >> 6, k0 = q * 64;
            float acc = 0.f;
            #pragma unroll 8
            for (int k = 0; k < 64; ++k)
                acc = fmaf(proto[k0 + k], w1[(k0 + k) * HID + c], acc);
            part[tid] = acc;
        }
        __syncthreads();
        if (tid < HID)
            h1[tid] = fmaxf(part[tid] + part[64 + tid] + part[128 + tid] + part[192 + tid] + b1[tid], 0.f);
        __syncthreads();

        // h2 = relu(h1 @ W2 + b2), 4-way split over k=64
        {
            const int c = tid & 63, q = tid >> 6, k0 = q * 16;
            float acc = 0.f;
            #pragma unroll
            for (int k = 0; k < 16; ++k)
                acc = fmaf(h1[k0 + k], w2[(k0 + k) * HID + c], acc);
            part[tid] = acc;
        }
        __syncthreads();
        if (tid < HID)
            h2[tid] = fmaxf(part[tid] + part[64 + tid] + part[128 + tid] + part[192 + tid] + b2[tid], 0.f);
        __syncthreads();

        // h3 = sigmoid(h2 @ W3 + b3)
        {
            float acc = b3[tid];
            #pragma unroll 8
            for (int k = 0; k < HID; ++k)
                acc = fmaf(h2[k], w3[k * FDIM + tid], acc);
            float v = __fdividef(1.0f, 1.0f + __expf(-acc));
            g_h3[tid] = v;
            h3S[tid]  = v;
        }
        __syncthreads();

        // base[c] = h3 @ (w1a+w1b) + eb1, 4-way k split
        {
            const int c = tid & 63, q = tid >> 6, k0 = q * 64;
            float acc = 0.f;
            #pragma unroll 4
            for (int k = 0; k < 64; ++k) {
                float w = ew1[(k0 + k) * HID + c] + ew1[EW1B_OFF + (k0 + k) * HID + c];
                acc = fmaf(h3S[k0 + k], w, acc);
            }
            part[tid] = acc;
        }
        __syncthreads();
        if (tid < HID)
            g_base[tid] = part[tid] + part[64 + tid] + part[128 + tid] + part[192 + tid] + eb1[tid];
        return;
    }

    // ---------------- noise GEMM (blocks 1..256), 8 rows each ----------------
    float* nS = sBuf;                       // [FDIM][NS_STRIDE] k-major
    const int r0 = (blockIdx.x - 1) * KP_ROWS;

    #pragma unroll
    for (int u = 0; u < KP_ROWS; ++u) {
        const int r = r0 + u;
        float v = 0.f;
        if (r >= TEMPLATE_N)
            v = 0.1f * noise[(size_t)(r - TEMPLATE_N) * FDIM + tid];
        nS[tid * NS_STRIDE + u] = v;
    }
    __syncthreads();

    const int c  = tid & 127;               // column (pa if <64, else pb)
    const int rh = tid >> 7;                // row half: 4 rows each
    const bool is_pa = (c < HID);
    const float* wcol = ew1 + (is_pa ? c : (EW1B_OFF + (c - HID)));

    unsigned long long acc0 = f2_pack(0.f, 0.f), acc1 = acc0;

    #pragma unroll 8
    for (int k = 0; k < FDIM; ++k) {
        const float w = wcol[k * HID];
        const unsigned long long wp = f2_pack(w, w);
        const ulonglong2 A = *reinterpret_cast<const ulonglong2*>(nS + k * NS_STRIDE + rh * 4);
        acc0 = f2_fma(A.x, wp, acc0);
        acc1 = f2_fma(A.y, wp, acc1);
    }

    float* dst = (is_pa ? g_npa : g_npb);
    const int cc = is_pa ? c : (c - HID);
    const int rb = r0 + rh * 4;
    float lo, hi;
    f2_unpack(lo, hi, acc0);
    dst[rb * HID + cc]       = lo;
    dst[(rb + 1) * HID + cc] = hi;
    f2_unpack(lo, hi, acc1);
    dst[(rb + 2) * HID + cc] = lo;
    dst[(rb + 3) * HID + cc] = hi;
}

// ---------------------------------------------------------------------------
// Kernel E: 288 tiles (256 j x 32 i), 256 threads, 2 CTAs/SM.
//   stage 0: trig rows (round-robin)
//   stage 1: pa(+base)->fp16 smem ; pb row + w2 -> fp16 regs
//   stage 2: i-loop unrolled x2, 8 independent HFMA2 chains
// ---------------------------------------------------------------------------
#define TI 32
#define TJ 256
#define N_TILES 288     // sum over jt of (8*jt + 8)

__global__ void __launch_bounds__(TJ, 2)
kE_edges(const float* __restrict__ noise,
         const float* __restrict__ ew2,
         const float* __restrict__ eb2,
         float* __restrict__ out_trig,
         float* __restrict__ out_edge)
{
    __shared__ __half2 paS[TI * 32];          // 4 KB
    const int tid = threadIdx.x;

    // ---- stage 0: trig rows ----
    {
        const float h3v = g_h3[tid];
        for (int r = blockIdx.x; r < N_NODES; r += N_TILES) {
            float v = h3v;
            if (r >= TEMPLATE_N)
                v = fmaf(0.1f, noise[(size_t)(r - TEMPLATE_N) * FDIM + tid], v);
            out_trig[(size_t)r * FDIM + tid] = v;
        }
    }

    // ---- tile mapping: block -> (jt, it); jt has 8*jt+8 i-tiles ----
    int rem = blockIdx.x, jt;
    for (jt = 0; jt < 8; ++jt) { const int n = 8 * jt + 8; if (rem < n) break; rem -= n; }
    const int it = rem;
    const int j0 = jt * TJ;
    const int i0 = it * TI;

    // ---- stage 1a: pa tile -> fp16 smem (base folded, fp32 add) ----
    for (int idx = tid; idx < TI * 32; idx += TJ) {
        const int ii = idx >> 5, kp = idx & 31;
        const float lo = g_npa[(i0 + ii) * HID + 2 * kp]     + g_base[2 * kp];
        const float hi = g_npa[(i0 + ii) * HID + 2 * kp + 1] + g_base[2 * kp + 1];
        paS[idx] = __floats2half2_rn(lo, hi);
    }

    // ---- stage 1b: pb row + w2 -> fp16 regs ----
    const int j = j0 + tid;
    __half2 pb2[32], w2h[32];
    {
        const float4* pbp = reinterpret_cast<const float4*>(g_npb + j * HID);
        const float4* w2p = reinterpret_cast<const float4*>(ew2);
        #pragma unroll
        for (int q = 0; q < 16; ++q) {
            float4 v = pbp[q];
            pb2[2 * q]     = __floats2half2_rn(v.x, v.y);
            pb2[2 * q + 1] = __floats2half2_rn(v.z, v.w);
            float4 w = __ldg(&w2p[q]);
            w2h[2 * q]     = __floats2half2_rn(w.x, w.y);
            w2h[2 * q + 1] = __floats2half2_rn(w.z, w.w);
        }
    }
    const float ebb = eb2[0];
    const __half2 one2 = __floats2half2_rn(1.0f, 1.0f);
    __syncthreads();

    // ---- stage 2: pair loop, 2 i's per iteration, 8 acc chains ----
    const uint4* paS4 = reinterpret_cast<const uint4*>(paS);   // 4 half2 per uint4

    #pragma unroll 2
    for (int ii = 0; ii < TI; ii += 2) {
        __half2 a0 = __float2half2_rn(0.f), a1 = a0, a2 = a0, a3 = a0;
        __half2 b0 = a0, b1 = a0, b2v = a0, b3v = a0;

        #pragma unroll
        for (int q = 0; q < 8; ++q) {
            const uint4 PA = paS4[ii * 8 + q];          // i = i0+ii
            const uint4 PB = paS4[(ii + 1) * 8 + q];    // i = i0+ii+1
            const int kp = q * 4;
            __half2 h;
            const __half2 pa0 = *reinterpret_cast<const __half2*>(&PA.x);
            const __half2 pa1 = *reinterpret_cast<const __half2*>(&PA.y);
            const __half2 pa2 = *reinterpret_cast<const __half2*>(&PA.z);
            const __half2 pa3 = *reinterpret_cast<const __half2*>(&PA.w);
            h = __hfma2_relu(pa0, one2, pb2[kp + 0]); a0 = __hfma2(h, w2h[kp + 0], a0);
            h = __hfma2_relu(pa1, one2, pb2[kp + 1]); a1 = __hfma2(h, w2h[kp + 1], a1);
            h = __hfma2_relu(pa2, one2, pb2[kp + 2]); a2 = __hfma2(h, w2h[kp + 2], a2);
            h = __hfma2_relu(pa3, one2, pb2[kp + 3]); a3 = __hfma2(h, w2h[kp + 3], a3);
            const __half2 qb0 = *reinterpret_cast<const __half2*>(&PB.x);
            const __half2 qb1 = *reinterpret_cast<const __half2*>(&PB.y);
            const __half2 qb2 = *reinterpret_cast<const __half2*>(&PB.z);
            const __half2 qb3 = *reinterpret_cast<const __half2*>(&PB.w);
            h = __hfma2_relu(qb0, one2, pb2[kp + 0]); b0  = __hfma2(h, w2h[kp + 0], b0);
            h = __hfma2_relu(qb1, one2, pb2[kp + 1]); b1  = __hfma2(h, w2h[kp + 1], b1);
            h = __hfma2_relu(qb2, one2, pb2[kp + 2]); b2v = __hfma2(h, w2h[kp + 2], b2v);
            h = __hfma2_relu(qb3, one2, pb2[kp + 3]); b3v = __hfma2(h, w2h[kp + 3], b3v);
        }

        {
            const int i = i0 + ii;
            if (j > i) {
                const __half2 st = __hadd2(__hadd2(a0, a1), __hadd2(a2, a3));
                const float2 f = __half22float2(st);
                const float s = f.x + f.y + ebb;
                const float pr = __fdividef(1.0f, 1.0f + __expf(-s));
                const int base = i * (2 * N_NODES - i - 1) / 2;
                out_edge[base + (j - i - 1)] = pr;
            }
        }
        {
            const int i = i0 + ii + 1;
            if (j > i) {
                const __half2 st = __hadd2(__hadd2(b0, b1), __hadd2(b2v, b3v));
                const float2 f = __half22float2(st);
                const float s = f.x + f.y + ebb;
                const float pr = __fdividef(1.0f, 1.0f + __expf(-s));
                const int base = i * (2 * N_NODES - i - 1) / 2;
                out_edge[base + (j - i - 1)] = pr;
            }
        }
    }
}

// ---------------------------------------------------------------------------
extern "C" void kernel_launch(void* const* d_in, const int* in_sizes, int n_in,
                              void* d_out, int out_size)
{
    const float* cf    = (const float*)d_in[0];
    const int*   sel   = (const int*)  d_in[1];
    const float* noise = (const float*)d_in[2];
    const float* g1w   = (const float*)d_in[3];
    const float* g1b   = (const float*)d_in[4];
    const float* g2w   = (const float*)d_in[5];
    const float* g2b   = (const float*)d_in[6];
    const float* g3w   = (const float*)d_in[7];
    const float* g3b   = (const float*)d_in[8];
    const float* ew1   = (const float*)d_in[9];
    const float* eb1   = (const float*)d_in[10];
    const float* ew2   = (const float*)d_in[11];
    const float* eb2   = (const float*)d_in[12];

    float* out      = (float*)d_out;
    float* out_trig = out;
    float* out_edge = out + TRIG_ELEMS;

    kP_prep<<<257, 256>>>(cf, sel, g1w, g1b, g2w, g2b, g3w, g3b, ew1, eb1, noise);
    kE_edges<<<N_TILES, TJ>>>(noise, ew2, eb2, out_trig, out_edge);
}